// round 10
// baseline (speedup 1.0000x reference)
#include <cuda_runtime.h>
#include <cuda_bf16.h>
#include <mma.h>
using namespace nvcuda;

#define NA    900
#define EMBED 256
#define NG    8
#define NCAM  6
#define NLVL  4
#define NPTS  13
#define NJ    312
#define NW    2496
#define SWP   324              // s_wT row stride (bank-spread: 324 % 32 = 4)

#define HW0 11264
#define HW1 2816
#define HW2 704
#define HW3 176
#define LOFF0 0
#define LOFF1 67584
#define LOFF2 84480
#define LOFF3 88704
#define TOTPX 89760
#define FMT_ELEMS (TOTPX * EMBED)

#define PB0 352
#define PB1 88
#define PB2 22
#define PB3 6
#define PBTOT 468

// ---------------- scratch ----------------
__device__ __nv_bfloat16 g_fmT[FMT_ELEMS];
__device__ float g_logits[NA * NW];
__device__ __nv_bfloat16 g_WoutB[EMBED * EMBED];
__device__ int4  g_off[NA * NJ];     // compacted corner byte-offsets
__device__ uint4 g_meta[NA * NJ];    // {geo_lo, geo_hi, tap_idx, 0}
__device__ int   g_nv[NA];

// ---------------- 1) fused transpose ---------------------------------------
__global__ __launch_bounds__(256) void k_transpose(const float* __restrict__ fm0,
                                                   const float* __restrict__ fm1,
                                                   const float* __restrict__ fm2,
                                                   const float* __restrict__ fm3) {
    __shared__ float tile[32][65];
    int bx = blockIdx.x;
    const float* fm;
    int HW, loff;
    if (bx < PB0)                  { fm = fm0; HW = HW0; loff = LOFF0; }
    else if (bx < PB0 + PB1)       { fm = fm1; HW = HW1; loff = LOFF1; bx -= PB0; }
    else if (bx < PB0 + PB1 + PB2) { fm = fm2; HW = HW2; loff = LOFF2; bx -= PB0 + PB1; }
    else                           { fm = fm3; HW = HW3; loff = LOFF3; bx -= PB0 + PB1 + PB2; }

    const int c   = blockIdx.z;
    const int ch0 = blockIdx.y * 64;
    const int px0 = bx * 32;
    const int tx = threadIdx.x, ty = threadIdx.y;   // (32, 8)

    int px = px0 + tx;
    if (px < HW) {
        #pragma unroll
        for (int k = 0; k < 8; k++)
            tile[tx][ty + 8 * k] = fm[(c * EMBED + ch0 + ty + 8 * k) * HW + px];
    }
    __syncthreads();
    #pragma unroll
    for (int k = 0; k < 4; k++) {
        int r  = ty + 8 * k;
        int pw = px0 + r;
        if (pw < HW) {
            __nv_bfloat162 v = __floats2bfloat162_rn(tile[r][2 * tx],
                                                     tile[r][2 * tx + 1]);
            *(__nv_bfloat162*)(g_fmT + (size_t)(loff + c * HW + pw) * EMBED
                               + ch0 + 2 * tx) = v;
        }
    }
}

// ---------------- 1b) Wout -> bf16 -----------------------------------------
__global__ __launch_bounds__(256) void k_wcvt(const float* __restrict__ Wout) {
    int t = (blockIdx.x * 256 + threadIdx.x) * 4;
    float4 v = *(const float4*)(Wout + t);
    __nv_bfloat162 lo = __floats2bfloat162_rn(v.x, v.y);
    __nv_bfloat162 hi = __floats2bfloat162_rn(v.z, v.w);
    *(uint2*)(g_WoutB + t) = make_uint2(*(unsigned*)&lo, *(unsigned*)&hi);
}

// ---------------- 1c) per-anchor tap geometry + compaction (input-only) ----
__global__ __launch_bounds__(320) void k_prep(const float* __restrict__ kp,
                                              const float* __restrict__ proj,
                                              const float* __restrict__ wh) {
    __shared__ float2 s_uv[NCAM * NPTS];
    __shared__ int s_nv;
    const int a = blockIdx.x;
    const int tid = threadIdx.x;

    if (tid == 0) s_nv = 0;
    if (tid < NCAM * NPTS) {
        int c = tid / NPTS, p = tid % NPTS;
        const float* k3 = kp + (a * NPTS + p) * 3;
        float x = k3[0], y = k3[1], z = k3[2];
        const float* M = proj + c * 16;
        float px = M[0]*x + M[1]*y + M[2]*z  + M[3];
        float py = M[4]*x + M[5]*y + M[6]*z  + M[7];
        float pd = fmaxf(M[8]*x + M[9]*y + M[10]*z + M[11], 1e-5f);
        float u = (px / pd) / wh[c*2+0] * 2.f - 1.f;
        float v = (py / pd) / wh[c*2+1] * 2.f - 1.f;
        s_uv[tid] = make_float2(u, v);
    }
    __syncthreads();

    const int t = tid;
    if (t < NJ) {
        int p  = t % NPTS;
        int cl = t / NPTS;
        int l  = cl & 3;
        int c  = cl >> 2;
        int Wl = 176 >> l, Hl = 64 >> l;
        int HWl  = 11264 >> (2 * l);
        int loff = (l >= 1 ? 67584 : 0) + (l >= 2 ? 16896 : 0) + (l >= 3 ? 4224 : 0);

        float2 uv = s_uv[c * NPTS + p];
        float gx = (uv.x + 1.f) * (Wl * 0.5f) - 0.5f;
        float gy = (uv.y + 1.f) * (Hl * 0.5f) - 0.5f;
        float x0f = floorf(gx), y0f = floorf(gy);
        float wx1 = gx - x0f,  wy1 = gy - y0f;
        float wx0 = 1.f - wx1, wy0 = 1.f - wy1;
        int x0 = (int)x0f, y0 = (int)y0f;
        bool vx0 = (x0 >= 0) && (x0 <= Wl - 1);
        bool vx1 = (x0 + 1 >= 0) && (x0 + 1 <= Wl - 1);
        bool vy0 = (y0 >= 0) && (y0 <= Hl - 1);
        bool vy1 = (y0 + 1 >= 0) && (y0 + 1 <= Hl - 1);
        if ((vx0 || vx1) && (vy0 || vy1)) {
            int x0c = min(max(x0, 0), Wl - 1);
            int x1c = min(max(x0 + 1, 0), Wl - 1);
            int y0c = min(max(y0, 0), Hl - 1);
            int y1c = min(max(y0 + 1, 0), Hl - 1);
            int base = loff + c * HWl;
            int4 off;
            off.x = (base + y0c * Wl + x0c) * EMBED * 2;
            off.y = (base + y0c * Wl + x1c) * EMBED * 2;
            off.z = (base + y1c * Wl + x0c) * EMBED * 2;
            off.w = (base + y1c * Wl + x1c) * EMBED * 2;

            float g00 = (vx0 && vy0) ? wx0 * wy0 : 0.f;
            float g01 = (vx1 && vy0) ? wx1 * wy0 : 0.f;
            float g10 = (vx0 && vy1) ? wx0 * wy1 : 0.f;
            float g11 = (vx1 && vy1) ? wx1 * wy1 : 0.f;
            __nv_bfloat162 lo = __floats2bfloat162_rn(g00, g01);
            __nv_bfloat162 hi = __floats2bfloat162_rn(g10, g11);

            int idx = atomicAdd(&s_nv, 1);
            g_off[a * NJ + idx]  = off;
            g_meta[a * NJ + idx] = make_uint4(*(unsigned*)&lo, *(unsigned*)&hi,
                                              (unsigned)t, 0u);
        }
    }
    __syncthreads();
    if (tid == 0) g_nv[a] = s_nv;
}

// ---------------- 2) weight GEMM: tf32 WMMA --------------------------------
#define GBM 64
#define GBN 64
#define GKB 32
#define ALDA (GKB + 8)
__global__ __launch_bounds__(256) void k_gemm_tc(const float* __restrict__ inst,
                                                 const float* __restrict__ anch,
                                                 const float* __restrict__ W,
                                                 const float* __restrict__ bias) {
    __shared__ float As[GBM][ALDA];
    __shared__ float Bs[GKB][GBN];
    __shared__ float Cs[GBM][GBN];

    const int tid  = threadIdx.x;
    const int warp = tid >> 5;
    const int wm   = warp >> 1;
    const int wn   = warp & 1;
    const int n0   = blockIdx.x * GBN;
    const int a0   = blockIdx.y * GBM;

    wmma::fragment<wmma::accumulator, 16, 16, 8, float> c0, c1;
    wmma::fill_fragment(c0, 0.0f);
    wmma::fill_fragment(c1, 0.0f);

    for (int k0 = 0; k0 < EMBED; k0 += GKB) {
        for (int t = tid; t < GBM * GKB / 4; t += 256) {
            int m  = t >> 3;
            int kc = (t & 7) * 4;
            float4 v = make_float4(0.f, 0.f, 0.f, 0.f);
            int ga = a0 + m;
            if (ga < NA) {
                float4 i4 = *(const float4*)(inst + ga * EMBED + k0 + kc);
                float4 a4 = *(const float4*)(anch + ga * EMBED + k0 + kc);
                v = make_float4(i4.x + a4.x, i4.y + a4.y, i4.z + a4.z, i4.w + a4.w);
            }
            *(float4*)&As[m][kc] = v;
        }
        for (int t = tid; t < GKB * GBN / 4; t += 256) {
            int kr = t >> 4;
            int nc = (t & 15) * 4;
            *(float4*)&Bs[kr][nc] = *(const float4*)(W + (k0 + kr) * NW + n0 + nc);
        }
        __syncthreads();
        #pragma unroll
        for (int kk = 0; kk < GKB; kk += 8) {
            wmma::fragment<wmma::matrix_a, 16, 16, 8, wmma::precision::tf32, wmma::row_major> af;
            wmma::fragment<wmma::matrix_b, 16, 16, 8, wmma::precision::tf32, wmma::row_major> bf0, bf1;
            wmma::load_matrix_sync(af, &As[wm * 16][kk], ALDA);
            wmma::load_matrix_sync(bf0, &Bs[kk][wn * 32], GBN);
            wmma::load_matrix_sync(bf1, &Bs[kk][wn * 32 + 16], GBN);
            #pragma unroll
            for (int i = 0; i < af.num_elements; i++)
                af.x[i] = wmma::__float_to_tf32(af.x[i]);
            #pragma unroll
            for (int i = 0; i < bf0.num_elements; i++) {
                bf0.x[i] = wmma::__float_to_tf32(bf0.x[i]);
                bf1.x[i] = wmma::__float_to_tf32(bf1.x[i]);
            }
            wmma::mma_sync(c0, af, bf0, c0);
            wmma::mma_sync(c1, af, bf1, c1);
        }
        __syncthreads();
    }
    wmma::store_matrix_sync(&Cs[wm * 16][wn * 32], c0, GBN, wmma::mem_row_major);
    wmma::store_matrix_sync(&Cs[wm * 16][wn * 32 + 16], c1, GBN, wmma::mem_row_major);
    __syncthreads();
    for (int t = tid; t < GBM * GBN / 4; t += 256) {
        int m  = t >> 4;
        int nc = (t & 15) * 4;
        int ga = a0 + m;
        if (ga >= NA) continue;
        float4 v = *(float4*)&Cs[m][nc];
        float4 bb = *(const float4*)(bias + n0 + nc);
        v.x += bb.x; v.y += bb.y; v.z += bb.z; v.w += bb.w;
        *(float4*)(g_logits + ga * NW + n0 + nc) = v;
    }
}

// ---------------- 3) softmax + streaming sample + GEMV ---------------------
// s_wT[g][j] (stride SWP) holds softmax weights through the gather loop;
// afterwards the same storage is re-used as s_part[8][256] + s_f. All
// aliasing is fenced by __syncthreads().
#define B2(u) (*(__nv_bfloat162*)&(u))
__global__ __launch_bounds__(256, 7) void k_sample(const float* __restrict__ inst,
                                                   const float* __restrict__ bout,
                                                   float* __restrict__ out) {
    __shared__ __align__(16) float s_wT[NG * SWP];   // 10368 B
    __shared__ int s_nv;
    float (*s_part)[EMBED] = (float(*)[EMBED])s_wT;
    float* s_f = s_wT + 2048;

    const int a = blockIdx.x;
    const int tid = threadIdx.x;

    if (tid == 0) s_nv = g_nv[a];
    {   // stage logits transposed: [j*8+g] -> s_wT[g*SWP + j]
        const float4* L4 = (const float4*)(g_logits + a * NW);
        for (int t = tid; t < NW / 4; t += 256) {
            float4 v = L4[t];
            int i0 = t * 4;
            int j  = i0 >> 3;
            int gb = i0 & 7;            // 0 or 4
            s_wT[(gb + 0) * SWP + j] = v.x;
            s_wT[(gb + 1) * SWP + j] = v.y;
            s_wT[(gb + 2) * SWP + j] = v.z;
            s_wT[(gb + 3) * SWP + j] = v.w;
        }
    }
    __syncthreads();

    {   // softmax per group (warp = group), conflict-free rows
        const int g = tid >> 5, lane = tid & 31;
        float* row = s_wT + g * SWP;
        float mx = -1e30f;
        for (int j = lane; j < NJ; j += 32) mx = fmaxf(mx, row[j]);
        #pragma unroll
        for (int o = 16; o; o >>= 1) mx = fmaxf(mx, __shfl_xor_sync(0xffffffffu, mx, o));
        float sum = 0.f;
        float vals[10];
        int cnt = 0;
        for (int j = lane; j < NJ; j += 32) {
            float e = __expf(row[j] - mx);
            vals[cnt++] = e;
            sum += e;
        }
        #pragma unroll
        for (int o = 16; o; o >>= 1) sum += __shfl_xor_sync(0xffffffffu, sum, o);
        float inv = 1.f / sum;
        cnt = 0;
        for (int j = lane; j < NJ; j += 32) row[j] = vals[cnt++] * inv;
    }
    __syncthreads();
    const int nv = s_nv;

    const int lane = tid & 31;
    const int tg   = tid >> 5;
    const int ch   = lane * 8;
    const int g    = lane >> 2;
    const char* fb = (const char*)g_fmT + ch * 2;
    const int4*  offp  = g_off  + a * NJ;
    const uint4* metap = g_meta + a * NJ;

    float acc[8] = {};
    #pragma unroll 2
    for (int i = tg; i < nv; i += 8) {
        int4  off = __ldg(offp + i);
        uint4 mt  = __ldg(metap + i);
        float wsm = s_wT[g * SWP + mt.z];
        __nv_bfloat162 glo = B2(mt.x), ghi = B2(mt.y);
        __nv_bfloat162 w00 = __low2bfloat162(glo), w01 = __high2bfloat162(glo);
        __nv_bfloat162 w10 = __low2bfloat162(ghi), w11 = __high2bfloat162(ghi);

        uint4 q00 = __ldg((const uint4*)(fb + off.x));
        uint4 q01 = __ldg((const uint4*)(fb + off.y));
        uint4 q10 = __ldg((const uint4*)(fb + off.z));
        uint4 q11 = __ldg((const uint4*)(fb + off.w));

        __nv_bfloat162 b0 = __hmul2(B2(q00.x), w00);
        __nv_bfloat162 b1 = __hmul2(B2(q00.y), w00);
        __nv_bfloat162 b2 = __hmul2(B2(q00.z), w00);
        __nv_bfloat162 b3 = __hmul2(B2(q00.w), w00);
        b0 = __hfma2(B2(q01.x), w01, b0);
        b1 = __hfma2(B2(q01.y), w01, b1);
        b2 = __hfma2(B2(q01.z), w01, b2);
        b3 = __hfma2(B2(q01.w), w01, b3);
        b0 = __hfma2(B2(q10.x), w10, b0);
        b1 = __hfma2(B2(q10.y), w10, b1);
        b2 = __hfma2(B2(q10.z), w10, b2);
        b3 = __hfma2(B2(q10.w), w10, b3);
        b0 = __hfma2(B2(q11.x), w11, b0);
        b1 = __hfma2(B2(q11.y), w11, b1);
        b2 = __hfma2(B2(q11.z), w11, b2);
        b3 = __hfma2(B2(q11.w), w11, b3);

        float2 f0 = __bfloat1622float2(b0);
        float2 f1 = __bfloat1622float2(b1);
        float2 f2 = __bfloat1622float2(b2);
        float2 f3 = __bfloat1622float2(b3);
        acc[0] = fmaf(wsm, f0.x, acc[0]); acc[1] = fmaf(wsm, f0.y, acc[1]);
        acc[2] = fmaf(wsm, f1.x, acc[2]); acc[3] = fmaf(wsm, f1.y, acc[3]);
        acc[4] = fmaf(wsm, f2.x, acc[4]); acc[5] = fmaf(wsm, f2.y, acc[5]);
        acc[6] = fmaf(wsm, f3.x, acc[6]); acc[7] = fmaf(wsm, f3.y, acc[7]);
    }
    __syncthreads();                 // s_wT dead; alias as s_part / s_f
    #pragma unroll
    for (int i = 0; i < 8; i++) s_part[tg][ch + i] = acc[i];
    __syncthreads();
    {
        float f = 0.f;
        #pragma unroll
        for (int k = 0; k < 8; k++) f += s_part[k][tid];
        s_f[tid] = f;
    }
    __syncthreads();

    // epilogue GEMV: out[a] = s_f @ Wout(bf16) + bias + inst
    const int j0 = lane * 8;
    const int kg = tg;
    float oa[8] = {};
    #pragma unroll 4
    for (int k = kg * 32; k < kg * 32 + 32; k++) {
        uint4 w = __ldg((const uint4*)(g_WoutB + k * EMBED + j0));
        float f = s_f[k];
        float2 w0 = __bfloat1622float2(B2(w.x));
        float2 w1 = __bfloat1622float2(B2(w.y));
        float2 w2 = __bfloat1622float2(B2(w.z));
        float2 w3 = __bfloat1622float2(B2(w.w));
        oa[0] += f * w0.x; oa[1] += f * w0.y;
        oa[2] += f * w1.x; oa[3] += f * w1.y;
        oa[4] += f * w2.x; oa[5] += f * w2.y;
        oa[6] += f * w3.x; oa[7] += f * w3.y;
    }
    __syncthreads();
    #pragma unroll
    for (int i = 0; i < 8; i++) s_part[kg][j0 + i] = oa[i];
    __syncthreads();
    {
        float v = 0.f;
        #pragma unroll
        for (int k = 0; k < 8; k++) v += s_part[k][tid];
        out[a * EMBED + tid] = v + bout[tid] + inst[a * EMBED + tid];
    }
}

// ---------------- launch ---------------------------------------------------
extern "C" void kernel_launch(void* const* d_in, const int* in_sizes, int n_in,
                              void* d_out, int out_size) {
    const float* inst = (const float*)d_in[0];
    const float* anch = (const float*)d_in[1];
    const float* kp   = (const float*)d_in[2];
    const float* fm0  = (const float*)d_in[3];
    const float* fm1  = (const float*)d_in[4];
    const float* fm2  = (const float*)d_in[5];
    const float* fm3  = (const float*)d_in[6];
    const float* proj = (const float*)d_in[7];
    const float* wh   = (const float*)d_in[8];
    const float* Ww   = (const float*)d_in[9];
    const float* bw   = (const float*)d_in[10];
    const float* Wo   = (const float*)d_in[11];
    const float* bo   = (const float*)d_in[12];
    float* out = (float*)d_out;

    static cudaStream_t s1 = nullptr;
    static cudaEvent_t eFork = nullptr, eJoin = nullptr;
    if (!s1) {
        cudaStreamCreateWithFlags(&s1, cudaStreamNonBlocking);
        cudaEventCreateWithFlags(&eFork, cudaEventDisableTiming);
        cudaEventCreateWithFlags(&eJoin, cudaEventDisableTiming);
    }

    cudaEventRecord(eFork, 0);
    cudaStreamWaitEvent(s1, eFork, 0);
    k_prep<<<NA, 320, 0, s1>>>(kp, proj, wh);
    k_gemm_tc<<<dim3(NW / GBN, (NA + GBM - 1) / GBM), 256, 0, s1>>>(inst, anch, Ww, bw);
    k_wcvt<<<EMBED * EMBED / 1024, 256, 0, s1>>>(Wo);
    cudaEventRecord(eJoin, s1);

    k_transpose<<<dim3(PBTOT, 4, NCAM), dim3(32, 8)>>>(fm0, fm1, fm2, fm3);

    cudaStreamWaitEvent(0, eJoin, 0);
    k_sample<<<NA, 256>>>(inst, bo, out);
}

// round 11
// speedup vs baseline: 1.0580x; 1.0580x over previous
#include <cuda_runtime.h>
#include <cuda_bf16.h>
#include <mma.h>
using namespace nvcuda;

#define NA    900
#define EMBED 256
#define NG    8
#define NCAM  6
#define NLVL  4
#define NPTS  13
#define NJ    312
#define NW    2496
#define SWP   324              // s_wT row stride (324 % 32 = 4 -> bank-spread)

#define HW0 11264
#define HW1 2816
#define HW2 704
#define HW3 176
#define LOFF0 0
#define LOFF1 67584
#define LOFF2 84480
#define LOFF3 88704
#define TOTPX 89760
#define FMT_ELEMS (TOTPX * EMBED)

#define PB0 352
#define PB1 88
#define PB2 22
#define PB3 6
#define PBTOT 468

// ---------------- scratch ----------------
__device__ __nv_bfloat16 g_fmT[FMT_ELEMS];
__device__ float g_logits[NA * NW];
__device__ __nv_bfloat16 g_WoutB[EMBED * EMBED];

// ---------------- 1) fused transpose ---------------------------------------
__global__ __launch_bounds__(256) void k_transpose(const float* __restrict__ fm0,
                                                   const float* __restrict__ fm1,
                                                   const float* __restrict__ fm2,
                                                   const float* __restrict__ fm3) {
    __shared__ float tile[32][65];
    int bx = blockIdx.x;
    const float* fm;
    int HW, loff;
    if (bx < PB0)                  { fm = fm0; HW = HW0; loff = LOFF0; }
    else if (bx < PB0 + PB1)       { fm = fm1; HW = HW1; loff = LOFF1; bx -= PB0; }
    else if (bx < PB0 + PB1 + PB2) { fm = fm2; HW = HW2; loff = LOFF2; bx -= PB0 + PB1; }
    else                           { fm = fm3; HW = HW3; loff = LOFF3; bx -= PB0 + PB1 + PB2; }

    const int c   = blockIdx.z;
    const int ch0 = blockIdx.y * 64;
    const int px0 = bx * 32;
    const int tx = threadIdx.x, ty = threadIdx.y;   // (32, 8)

    int px = px0 + tx;
    if (px < HW) {
        #pragma unroll
        for (int k = 0; k < 8; k++)
            tile[tx][ty + 8 * k] = fm[(c * EMBED + ch0 + ty + 8 * k) * HW + px];
    }
    __syncthreads();
    #pragma unroll
    for (int k = 0; k < 4; k++) {
        int r  = ty + 8 * k;
        int pw = px0 + r;
        if (pw < HW) {
            __nv_bfloat162 v = __floats2bfloat162_rn(tile[r][2 * tx],
                                                     tile[r][2 * tx + 1]);
            *(__nv_bfloat162*)(g_fmT + (size_t)(loff + c * HW + pw) * EMBED
                               + ch0 + 2 * tx) = v;
        }
    }
}

// ---------------- 1b) Wout -> bf16 -----------------------------------------
__global__ __launch_bounds__(256) void k_wcvt(const float* __restrict__ Wout) {
    int t = (blockIdx.x * 256 + threadIdx.x) * 4;
    float4 v = *(const float4*)(Wout + t);
    __nv_bfloat162 lo = __floats2bfloat162_rn(v.x, v.y);
    __nv_bfloat162 hi = __floats2bfloat162_rn(v.z, v.w);
    *(uint2*)(g_WoutB + t) = make_uint2(*(unsigned*)&lo, *(unsigned*)&hi);
}

// ---------------- 2) weight GEMM: tf32 WMMA --------------------------------
#define GBM 64
#define GBN 64
#define GKB 32
#define ALDA (GKB + 8)
__global__ __launch_bounds__(256) void k_gemm_tc(const float* __restrict__ inst,
                                                 const float* __restrict__ anch,
                                                 const float* __restrict__ W,
                                                 const float* __restrict__ bias) {
    __shared__ float As[GBM][ALDA];
    __shared__ float Bs[GKB][GBN];
    __shared__ float Cs[GBM][GBN];

    const int tid  = threadIdx.x;
    const int warp = tid >> 5;
    const int wm   = warp >> 1;
    const int wn   = warp & 1;
    const int n0   = blockIdx.x * GBN;
    const int a0   = blockIdx.y * GBM;

    wmma::fragment<wmma::accumulator, 16, 16, 8, float> c0, c1;
    wmma::fill_fragment(c0, 0.0f);
    wmma::fill_fragment(c1, 0.0f);

    for (int k0 = 0; k0 < EMBED; k0 += GKB) {
        for (int t = tid; t < GBM * GKB / 4; t += 256) {
            int m  = t >> 3;
            int kc = (t & 7) * 4;
            float4 v = make_float4(0.f, 0.f, 0.f, 0.f);
            int ga = a0 + m;
            if (ga < NA) {
                float4 i4 = *(const float4*)(inst + ga * EMBED + k0 + kc);
                float4 a4 = *(const float4*)(anch + ga * EMBED + k0 + kc);
                v = make_float4(i4.x + a4.x, i4.y + a4.y, i4.z + a4.z, i4.w + a4.w);
            }
            *(float4*)&As[m][kc] = v;
        }
        for (int t = tid; t < GKB * GBN / 4; t += 256) {
            int kr = t >> 4;
            int nc = (t & 15) * 4;
            *(float4*)&Bs[kr][nc] = *(const float4*)(W + (k0 + kr) * NW + n0 + nc);
        }
        __syncthreads();
        #pragma unroll
        for (int kk = 0; kk < GKB; kk += 8) {
            wmma::fragment<wmma::matrix_a, 16, 16, 8, wmma::precision::tf32, wmma::row_major> af;
            wmma::fragment<wmma::matrix_b, 16, 16, 8, wmma::precision::tf32, wmma::row_major> bf0, bf1;
            wmma::load_matrix_sync(af, &As[wm * 16][kk], ALDA);
            wmma::load_matrix_sync(bf0, &Bs[kk][wn * 32], GBN);
            wmma::load_matrix_sync(bf1, &Bs[kk][wn * 32 + 16], GBN);
            #pragma unroll
            for (int i = 0; i < af.num_elements; i++)
                af.x[i] = wmma::__float_to_tf32(af.x[i]);
            #pragma unroll
            for (int i = 0; i < bf0.num_elements; i++) {
                bf0.x[i] = wmma::__float_to_tf32(bf0.x[i]);
                bf1.x[i] = wmma::__float_to_tf32(bf1.x[i]);
            }
            wmma::mma_sync(c0, af, bf0, c0);
            wmma::mma_sync(c1, af, bf1, c1);
        }
        __syncthreads();
    }
    wmma::store_matrix_sync(&Cs[wm * 16][wn * 32], c0, GBN, wmma::mem_row_major);
    wmma::store_matrix_sync(&Cs[wm * 16][wn * 32 + 16], c1, GBN, wmma::mem_row_major);
    __syncthreads();
    for (int t = tid; t < GBM * GBN / 4; t += 256) {
        int m  = t >> 4;
        int nc = (t & 15) * 4;
        int ga = a0 + m;
        if (ga >= NA) continue;
        float4 v = *(float4*)&Cs[m][nc];
        float4 bb = *(const float4*)(bias + n0 + nc);
        v.x += bb.x; v.y += bb.y; v.z += bb.z; v.w += bb.w;
        *(float4*)(g_logits + ga * NW + n0 + nc) = v;
    }
}

// ---------------- 3) fused uv + softmax + compacted sampling + GEMV --------
// Tap records live in SMEM (packed): s_base = corner00 byte offset,
// s_ft = tap | l<<9 | dx<<11 | dy<<12, s_g4 = 4x bf16 geometric weights.
// s_wT[g][j] holds softmax weights through the gather loop, then the same
// storage is aliased as s_part[8][256] + s_f. All reuse fenced by syncs.
#define B2(u) (*(__nv_bfloat162*)&(u))
__global__ __launch_bounds__(256, 8) void k_sample(const float* __restrict__ kp,
                                                   const float* __restrict__ proj,
                                                   const float* __restrict__ wh,
                                                   const float* __restrict__ inst,
                                                   const float* __restrict__ bout,
                                                   float* __restrict__ out) {
    __shared__ __align__(16) float s_wT[NG * SWP];   // 10368 B
    __shared__ float2   s_uv[NCAM * NPTS];           //   624 B
    __shared__ int      s_base[NJ];                  //  1248 B
    __shared__ unsigned s_ft[NJ];                    //  1248 B
    __shared__ uint2    s_g4[NJ];                    //  2496 B
    __shared__ int      s_nv;
    float (*s_part)[EMBED] = (float(*)[EMBED])s_wT;
    float* s_f = s_wT + 2048;

    const int a = blockIdx.x;
    const int tid = threadIdx.x;

    if (tid == 0) s_nv = 0;
    {   // stage logits transposed: [j*8+g] -> s_wT[g*SWP + j]
        const float4* L4 = (const float4*)(g_logits + a * NW);
        for (int t = tid; t < NW / 4; t += 256) {
            float4 v = L4[t];
            int i0 = t * 4;
            int j  = i0 >> 3;
            int gb = i0 & 7;            // 0 or 4
            s_wT[(gb + 0) * SWP + j] = v.x;
            s_wT[(gb + 1) * SWP + j] = v.y;
            s_wT[(gb + 2) * SWP + j] = v.z;
            s_wT[(gb + 3) * SWP + j] = v.w;
        }
    }
    if (tid < NCAM * NPTS) {   // project key points
        int c = tid / NPTS, p = tid % NPTS;
        const float* k3 = kp + (a * NPTS + p) * 3;
        float x = k3[0], y = k3[1], z = k3[2];
        const float* M = proj + c * 16;
        float px = M[0]*x + M[1]*y + M[2]*z  + M[3];
        float py = M[4]*x + M[5]*y + M[6]*z  + M[7];
        float pd = fmaxf(M[8]*x + M[9]*y + M[10]*z + M[11], 1e-5f);
        float u = (px / pd) / wh[c*2+0] * 2.f - 1.f;
        float v = (py / pd) / wh[c*2+1] * 2.f - 1.f;
        s_uv[tid] = make_float2(u, v);
    }
    __syncthreads();

    {   // softmax per group (warp = group), conflict-free rows
        const int g = tid >> 5, lane = tid & 31;
        float* row = s_wT + g * SWP;
        float mx = -1e30f;
        for (int j = lane; j < NJ; j += 32) mx = fmaxf(mx, row[j]);
        #pragma unroll
        for (int o = 16; o; o >>= 1) mx = fmaxf(mx, __shfl_xor_sync(0xffffffffu, mx, o));
        float sum = 0.f;
        float vals[10];
        int cnt = 0;
        for (int j = lane; j < NJ; j += 32) {
            float e = __expf(row[j] - mx);
            vals[cnt++] = e;
            sum += e;
        }
        #pragma unroll
        for (int o = 16; o; o >>= 1) sum += __shfl_xor_sync(0xffffffffu, sum, o);
        float inv = 1.f / sum;
        cnt = 0;
        for (int j = lane; j < NJ; j += 32) row[j] = vals[cnt++] * inv;
    }

    // per-tap geometry; compact: only taps with >=1 valid corner survive
    for (int t = tid; t < NJ; t += 256) {
        int p  = t % NPTS;
        int cl = t / NPTS;
        int l  = cl & 3;
        int c  = cl >> 2;
        int Wl = 176 >> l, Hl = 64 >> l;
        int HWl  = 11264 >> (2 * l);
        int loff = (l >= 1 ? 67584 : 0) + (l >= 2 ? 16896 : 0) + (l >= 3 ? 4224 : 0);

        float2 uv = s_uv[c * NPTS + p];
        float gx = (uv.x + 1.f) * (Wl * 0.5f) - 0.5f;
        float gy = (uv.y + 1.f) * (Hl * 0.5f) - 0.5f;
        float x0f = floorf(gx), y0f = floorf(gy);
        float wx1 = gx - x0f,  wy1 = gy - y0f;
        float wx0 = 1.f - wx1, wy0 = 1.f - wy1;
        int x0 = (int)x0f, y0 = (int)y0f;
        bool vx0 = (x0 >= 0) && (x0 <= Wl - 1);
        bool vx1 = (x0 + 1 >= 0) && (x0 + 1 <= Wl - 1);
        bool vy0 = (y0 >= 0) && (y0 <= Hl - 1);
        bool vy1 = (y0 + 1 >= 0) && (y0 + 1 <= Hl - 1);
        if (!((vx0 || vx1) && (vy0 || vy1))) continue;

        int x0c = min(max(x0, 0), Wl - 1);
        int x1c = min(max(x0 + 1, 0), Wl - 1);
        int y0c = min(max(y0, 0), Hl - 1);
        int y1c = min(max(y0 + 1, 0), Hl - 1);

        float g00 = (vx0 && vy0) ? wx0 * wy0 : 0.f;
        float g01 = (vx1 && vy0) ? wx1 * wy0 : 0.f;
        float g10 = (vx0 && vy1) ? wx0 * wy1 : 0.f;
        float g11 = (vx1 && vy1) ? wx1 * wy1 : 0.f;

        unsigned dx = (x1c != x0c) ? 1u : 0u;
        unsigned dy = (y1c != y0c) ? 1u : 0u;

        int idx = atomicAdd(&s_nv, 1);
        s_base[idx] = (loff + c * HWl + y0c * Wl + x0c) * (EMBED * 2);
        s_ft[idx]   = (unsigned)t | ((unsigned)l << 9) | (dx << 11) | (dy << 12);
        __nv_bfloat162 lo = __floats2bfloat162_rn(g00, g01);
        __nv_bfloat162 hi = __floats2bfloat162_rn(g10, g11);
        s_g4[idx] = make_uint2(*(unsigned*)&lo, *(unsigned*)&hi);
    }
    __syncthreads();
    const int nv = s_nv;

    const int lane = tid & 31;
    const int tg   = tid >> 5;
    const int ch   = lane * 8;
    const int g    = lane >> 2;
    const char* fb = (const char*)g_fmT + ch * 2;

    float acc[8] = {};
    #pragma unroll 2
    for (int i = tg; i < nv; i += 8) {
        int      base = s_base[i];
        unsigned ft   = s_ft[i];
        uint2    gp   = s_g4[i];
        int l   = (ft >> 9) & 3;
        int dxo = ((ft >> 11) & 1) << 9;          // 0 or 512
        int dyo = (ft & 0x1000) ? (90112 >> l) : 0;
        float wsm = s_wT[g * SWP + (ft & 0x1FF)];

        __nv_bfloat162 glo = B2(gp.x), ghi = B2(gp.y);
        __nv_bfloat162 w00 = __low2bfloat162(glo), w01 = __high2bfloat162(glo);
        __nv_bfloat162 w10 = __low2bfloat162(ghi), w11 = __high2bfloat162(ghi);

        uint4 q00 = __ldg((const uint4*)(fb + base));
        uint4 q01 = __ldg((const uint4*)(fb + base + dxo));
        uint4 q10 = __ldg((const uint4*)(fb + base + dyo));
        uint4 q11 = __ldg((const uint4*)(fb + base + dyo + dxo));

        __nv_bfloat162 b0 = __hmul2(B2(q00.x), w00);
        __nv_bfloat162 b1 = __hmul2(B2(q00.y), w00);
        __nv_bfloat162 b2 = __hmul2(B2(q00.z), w00);
        __nv_bfloat162 b3 = __hmul2(B2(q00.w), w00);
        b0 = __hfma2(B2(q01.x), w01, b0);
        b1 = __hfma2(B2(q01.y), w01, b1);
        b2 = __hfma2(B2(q01.z), w01, b2);
        b3 = __hfma2(B2(q01.w), w01, b3);
        b0 = __hfma2(B2(q10.x), w10, b0);
        b1 = __hfma2(B2(q10.y), w10, b1);
        b2 = __hfma2(B2(q10.z), w10, b2);
        b3 = __hfma2(B2(q10.w), w10, b3);
        b0 = __hfma2(B2(q11.x), w11, b0);
        b1 = __hfma2(B2(q11.y), w11, b1);
        b2 = __hfma2(B2(q11.z), w11, b2);
        b3 = __hfma2(B2(q11.w), w11, b3);

        float2 f0 = __bfloat1622float2(b0);
        float2 f1 = __bfloat1622float2(b1);
        float2 f2 = __bfloat1622float2(b2);
        float2 f3 = __bfloat1622float2(b3);
        acc[0] = fmaf(wsm, f0.x, acc[0]); acc[1] = fmaf(wsm, f0.y, acc[1]);
        acc[2] = fmaf(wsm, f1.x, acc[2]); acc[3] = fmaf(wsm, f1.y, acc[3]);
        acc[4] = fmaf(wsm, f2.x, acc[4]); acc[5] = fmaf(wsm, f2.y, acc[5]);
        acc[6] = fmaf(wsm, f3.x, acc[6]); acc[7] = fmaf(wsm, f3.y, acc[7]);
    }
    __syncthreads();                 // s_wT dead; alias as s_part / s_f
    #pragma unroll
    for (int i = 0; i < 8; i++) s_part[tg][ch + i] = acc[i];
    __syncthreads();
    {
        float f = 0.f;
        #pragma unroll
        for (int k = 0; k < 8; k++) f += s_part[k][tid];
        s_f[tid] = f;
    }
    __syncthreads();

    // epilogue GEMV: out[a] = s_f @ Wout(bf16) + bias + inst
    const int j0 = lane * 8;
    const int kg = tg;
    float oa[8] = {};
    #pragma unroll 4
    for (int k = kg * 32; k < kg * 32 + 32; k++) {
        uint4 w = __ldg((const uint4*)(g_WoutB + k * EMBED + j0));
        float f = s_f[k];
        float2 w0 = __bfloat1622float2(B2(w.x));
        float2 w1 = __bfloat1622float2(B2(w.y));
        float2 w2 = __bfloat1622float2(B2(w.z));
        float2 w3 = __bfloat1622float2(B2(w.w));
        oa[0] += f * w0.x; oa[1] += f * w0.y;
        oa[2] += f * w1.x; oa[3] += f * w1.y;
        oa[4] += f * w2.x; oa[5] += f * w2.y;
        oa[6] += f * w3.x; oa[7] += f * w3.y;
    }
    __syncthreads();
    #pragma unroll
    for (int i = 0; i < 8; i++) s_part[kg][j0 + i] = oa[i];
    __syncthreads();
    {
        float v = 0.f;
        #pragma unroll
        for (int k = 0; k < 8; k++) v += s_part[k][tid];
        out[a * EMBED + tid] = v + bout[tid] + inst[a * EMBED + tid];
    }
}

// ---------------- launch: fork gemm/wcvt parallel to transpose -------------
extern "C" void kernel_launch(void* const* d_in, const int* in_sizes, int n_in,
                              void* d_out, int out_size) {
    const float* inst = (const float*)d_in[0];
    const float* anch = (const float*)d_in[1];
    const float* kp   = (const float*)d_in[2];
    const float* fm0  = (const float*)d_in[3];
    const float* fm1  = (const float*)d_in[4];
    const float* fm2  = (const float*)d_in[5];
    const float* fm3  = (const float*)d_in[6];
    const float* proj = (const float*)d_in[7];
    const float* wh   = (const float*)d_in[8];
    const float* Ww   = (const float*)d_in[9];
    const float* bw   = (const float*)d_in[10];
    const float* Wo   = (const float*)d_in[11];
    const float* bo   = (const float*)d_in[12];
    float* out = (float*)d_out;

    static cudaStream_t s1 = nullptr;
    static cudaEvent_t eFork = nullptr, eJoin = nullptr;
    if (!s1) {
        cudaStreamCreateWithFlags(&s1, cudaStreamNonBlocking);
        cudaEventCreateWithFlags(&eFork, cudaEventDisableTiming);
        cudaEventCreateWithFlags(&eJoin, cudaEventDisableTiming);
        cudaFuncSetAttribute((const void*)k_sample,
                             cudaFuncAttributePreferredSharedMemoryCarveout, 60);
    }

    cudaEventRecord(eFork, 0);
    cudaStreamWaitEvent(s1, eFork, 0);
    k_gemm_tc<<<dim3(NW / GBN, (NA + GBM - 1) / GBM), 256, 0, s1>>>(inst, anch, Ww, bw);
    k_wcvt<<<EMBED * EMBED / 1024, 256, 0, s1>>>(Wo);
    cudaEventRecord(eJoin, s1);

    k_transpose<<<dim3(PBTOT, 4, NCAM), dim3(32, 8)>>>(fm0, fm1, fm2, fm3);

    cudaStreamWaitEvent(0, eJoin, 0);
    k_sample<<<NA, 256>>>(kp, proj, wh, inst, bo, out);
}

// round 12
// speedup vs baseline: 1.6198x; 1.5310x over previous
#include <cuda_runtime.h>
#include <cuda_bf16.h>
#include <mma.h>
using namespace nvcuda;

#define NA    900
#define EMBED 256
#define NG    8
#define NCAM  6
#define NLVL  4
#define NPTS  13
#define NJ    312
#define NW    2496

#define HW0 11264
#define HW1 2816
#define HW2 704
#define HW3 176
#define LOFF0 0
#define LOFF1 67584
#define LOFF2 84480
#define LOFF3 88704
#define TOTPX 89760
#define FMT_ELEMS (TOTPX * EMBED)

#define PB0 352
#define PB1 88
#define PB2 22
#define PB3 6
#define PBTOT 468

// ---------------- scratch ----------------
__device__ __nv_bfloat16 g_fmT[FMT_ELEMS];
__device__ float g_logits[NA * NW];
__device__ __nv_bfloat16 g_WoutB[EMBED * EMBED];
__device__ __nv_bfloat16 g_featB[960 * EMBED];      // feat = inst+anchor, bf16 (padded rows)
__device__ __nv_bfloat16 g_WB[EMBED * NW];          // weight matrix, bf16

// ---------------- 1) fused transpose ---------------------------------------
__global__ __launch_bounds__(256) void k_transpose(const float* __restrict__ fm0,
                                                   const float* __restrict__ fm1,
                                                   const float* __restrict__ fm2,
                                                   const float* __restrict__ fm3) {
    __shared__ float tile[32][65];
    int bx = blockIdx.x;
    const float* fm;
    int HW, loff;
    if (bx < PB0)                  { fm = fm0; HW = HW0; loff = LOFF0; }
    else if (bx < PB0 + PB1)       { fm = fm1; HW = HW1; loff = LOFF1; bx -= PB0; }
    else if (bx < PB0 + PB1 + PB2) { fm = fm2; HW = HW2; loff = LOFF2; bx -= PB0 + PB1; }
    else                           { fm = fm3; HW = HW3; loff = LOFF3; bx -= PB0 + PB1 + PB2; }

    const int c   = blockIdx.z;
    const int ch0 = blockIdx.y * 64;
    const int px0 = bx * 32;
    const int tx = threadIdx.x, ty = threadIdx.y;   // (32, 8)

    int px = px0 + tx;
    if (px < HW) {
        #pragma unroll
        for (int k = 0; k < 8; k++)
            tile[tx][ty + 8 * k] = fm[(c * EMBED + ch0 + ty + 8 * k) * HW + px];
    }
    __syncthreads();
    #pragma unroll
    for (int k = 0; k < 4; k++) {
        int r  = ty + 8 * k;
        int pw = px0 + r;
        if (pw < HW) {
            __nv_bfloat162 v = __floats2bfloat162_rn(tile[r][2 * tx],
                                                     tile[r][2 * tx + 1]);
            *(__nv_bfloat162*)(g_fmT + (size_t)(loff + c * HW + pw) * EMBED
                               + ch0 + 2 * tx) = v;
        }
    }
}

// ---------------- 1b) Wout -> bf16 -----------------------------------------
__global__ __launch_bounds__(256) void k_wcvt(const float* __restrict__ Wout) {
    int t = (blockIdx.x * 256 + threadIdx.x) * 4;
    float4 v = *(const float4*)(Wout + t);
    __nv_bfloat162 lo = __floats2bfloat162_rn(v.x, v.y);
    __nv_bfloat162 hi = __floats2bfloat162_rn(v.z, v.w);
    *(uint2*)(g_WoutB + t) = make_uint2(*(unsigned*)&lo, *(unsigned*)&hi);
}

// ---------------- 1c) feat = inst + anchor -> bf16 -------------------------
__global__ __launch_bounds__(256) void k_fcvt(const float* __restrict__ inst,
                                              const float* __restrict__ anch) {
    int t = (blockIdx.x * 256 + threadIdx.x) * 4;
    if (t >= NA * EMBED) return;
    float4 i4 = *(const float4*)(inst + t);
    float4 a4 = *(const float4*)(anch + t);
    __nv_bfloat162 lo = __floats2bfloat162_rn(i4.x + a4.x, i4.y + a4.y);
    __nv_bfloat162 hi = __floats2bfloat162_rn(i4.z + a4.z, i4.w + a4.w);
    *(uint2*)(g_featB + t) = make_uint2(*(unsigned*)&lo, *(unsigned*)&hi);
}

// ---------------- 1d) W -> bf16 --------------------------------------------
__global__ __launch_bounds__(256) void k_wwcvt(const float* __restrict__ W) {
    int t = (blockIdx.x * 256 + threadIdx.x) * 4;
    float4 v = *(const float4*)(W + t);
    __nv_bfloat162 lo = __floats2bfloat162_rn(v.x, v.y);
    __nv_bfloat162 hi = __floats2bfloat162_rn(v.z, v.w);
    *(uint2*)(g_WB + t) = make_uint2(*(unsigned*)&lo, *(unsigned*)&hi);
}

// ---------------- 2) weight GEMM: bf16 WMMA, BK=64 -------------------------
#define GBM 64
#define GBN 64
#define GKB 64
#define ASTR 72     // smem row stride in halves (144B, 16B-aligned)
__global__ __launch_bounds__(256) void k_gemm_bf(const float* __restrict__ bias) {
    __shared__ __nv_bfloat16 As[GBM][ASTR];
    __shared__ __nv_bfloat16 Bs[GKB][ASTR];
    __shared__ float Cs[GBM][GBN];

    const int tid  = threadIdx.x;
    const int warp = tid >> 5;
    const int wm   = warp >> 1;      // 0..3
    const int wn   = warp & 1;       // 0..1
    const int n0   = blockIdx.x * GBN;
    const int a0   = blockIdx.y * GBM;

    wmma::fragment<wmma::accumulator, 16, 16, 16, float> c0, c1;
    wmma::fill_fragment(c0, 0.0f);
    wmma::fill_fragment(c1, 0.0f);

    for (int k0 = 0; k0 < EMBED; k0 += GKB) {
        // A tile: 64 rows x 64 k halves = 512 uint4 slots, 2 per thread
        #pragma unroll
        for (int s = tid; s < GBM * GKB / 8; s += 256) {
            int row  = s >> 3;
            int col8 = (s & 7) * 8;
            uint4 v = make_uint4(0u, 0u, 0u, 0u);
            // g_featB rows padded to 960; rows >= NA are garbage but masked at store
            v = *(const uint4*)(g_featB + (a0 + row) * EMBED + k0 + col8);
            *(uint4*)&As[row][col8] = v;
        }
        // B tile: 64 k x 64 n
        #pragma unroll
        for (int s = tid; s < GKB * GBN / 8; s += 256) {
            int krow = s >> 3;
            int col8 = (s & 7) * 8;
            *(uint4*)&Bs[krow][col8] =
                *(const uint4*)(g_WB + (k0 + krow) * NW + n0 + col8);
        }
        __syncthreads();
        #pragma unroll
        for (int kk = 0; kk < GKB; kk += 16) {
            wmma::fragment<wmma::matrix_a, 16, 16, 16, __nv_bfloat16, wmma::row_major> af;
            wmma::fragment<wmma::matrix_b, 16, 16, 16, __nv_bfloat16, wmma::row_major> bf0, bf1;
            wmma::load_matrix_sync(af, &As[wm * 16][kk], ASTR);
            wmma::load_matrix_sync(bf0, &Bs[kk][wn * 32], ASTR);
            wmma::load_matrix_sync(bf1, &Bs[kk][wn * 32 + 16], ASTR);
            wmma::mma_sync(c0, af, bf0, c0);
            wmma::mma_sync(c1, af, bf1, c1);
        }
        __syncthreads();
    }
    wmma::store_matrix_sync(&Cs[wm * 16][wn * 32], c0, GBN, wmma::mem_row_major);
    wmma::store_matrix_sync(&Cs[wm * 16][wn * 32 + 16], c1, GBN, wmma::mem_row_major);
    __syncthreads();
    for (int t = tid; t < GBM * GBN / 4; t += 256) {
        int m  = t >> 4;
        int nc = (t & 15) * 4;
        int ga = a0 + m;
        if (ga >= NA) continue;
        float4 v = *(float4*)&Cs[m][nc];
        float4 bb = *(const float4*)(bias + n0 + nc);
        v.x += bb.x; v.y += bb.y; v.z += bb.z; v.w += bb.w;
        *(float4*)(g_logits + ga * NW + n0 + nc) = v;
    }
}

// ---------------- 3) fused uv + softmax + compacted sampling + GEMV --------
// (exact R9 sampler — measured 53.8us)
#define B2(u) (*(__nv_bfloat162*)&(u))
__global__ __launch_bounds__(256, 7) void k_sample(const float* __restrict__ kp,
                                                   const float* __restrict__ proj,
                                                   const float* __restrict__ wh,
                                                   const float* __restrict__ inst,
                                                   const float* __restrict__ bout,
                                                   float* __restrict__ out) {
    __shared__ __align__(16) float s_mix[NW];    // 9984 B
    __shared__ float2 s_uv[NCAM * NPTS];         // 624 B
    __shared__ int4   s_off[NJ];                 // 4992 B
    __shared__ uint2  s_g4[NJ];                  // 2496 B
    __shared__ int    s_tap[NJ];                 // 1248 B
    __shared__ int    s_nv;
    float* s_w = s_mix;
    float (*s_part)[EMBED] = (float(*)[EMBED])s_mix;
    float* s_f = s_mix + 2048;

    const int a = blockIdx.x;
    const int tid = threadIdx.x;

    if (tid == 0) s_nv = 0;
    {   // stage logits
        const float4* L4 = (const float4*)(g_logits + a * NW);
        float4* S4 = (float4*)s_w;
        for (int t = tid; t < NW / 4; t += 256) S4[t] = L4[t];
    }
    if (tid < NCAM * NPTS) {   // project key points
        int c = tid / NPTS, p = tid % NPTS;
        const float* k3 = kp + (a * NPTS + p) * 3;
        float x = k3[0], y = k3[1], z = k3[2];
        const float* M = proj + c * 16;
        float px = M[0]*x + M[1]*y + M[2]*z  + M[3];
        float py = M[4]*x + M[5]*y + M[6]*z  + M[7];
        float pd = fmaxf(M[8]*x + M[9]*y + M[10]*z + M[11], 1e-5f);
        float u = (px / pd) / wh[c*2+0] * 2.f - 1.f;
        float v = (py / pd) / wh[c*2+1] * 2.f - 1.f;
        s_uv[tid] = make_float2(u, v);
    }
    __syncthreads();

    {   // softmax per group (warp = group); result stays in s_w
        const int g = tid >> 5, lane = tid & 31;
        float mx = -1e30f;
        for (int j = lane; j < NJ; j += 32) mx = fmaxf(mx, s_w[j * NG + g]);
        #pragma unroll
        for (int o = 16; o; o >>= 1) mx = fmaxf(mx, __shfl_xor_sync(0xffffffffu, mx, o));
        float sum = 0.f;
        float vals[10];
        int cnt = 0;
        for (int j = lane; j < NJ; j += 32) {
            float e = __expf(s_w[j * NG + g] - mx);
            vals[cnt++] = e;
            sum += e;
        }
        #pragma unroll
        for (int o = 16; o; o >>= 1) sum += __shfl_xor_sync(0xffffffffu, sum, o);
        float inv = 1.f / sum;
        cnt = 0;
        for (int j = lane; j < NJ; j += 32) s_w[j * NG + g] = vals[cnt++] * inv;
    }
    __syncthreads();

    // per-tap geometry; compact: only taps with >=1 valid corner survive
    for (int t = tid; t < NJ; t += 256) {
        int p  = t % NPTS;
        int cl = t / NPTS;
        int l  = cl & 3;
        int c  = cl >> 2;
        int Wl = 176 >> l, Hl = 64 >> l;
        int HWl  = 11264 >> (2 * l);
        int loff = (l >= 1 ? 67584 : 0) + (l >= 2 ? 16896 : 0) + (l >= 3 ? 4224 : 0);

        float2 uv = s_uv[c * NPTS + p];
        float gx = (uv.x + 1.f) * (Wl * 0.5f) - 0.5f;
        float gy = (uv.y + 1.f) * (Hl * 0.5f) - 0.5f;
        float x0f = floorf(gx), y0f = floorf(gy);
        float wx1 = gx - x0f,  wy1 = gy - y0f;
        float wx0 = 1.f - wx1, wy0 = 1.f - wy1;
        int x0 = (int)x0f, y0 = (int)y0f;
        bool vx0 = (x0 >= 0) && (x0 <= Wl - 1);
        bool vx1 = (x0 + 1 >= 0) && (x0 + 1 <= Wl - 1);
        bool vy0 = (y0 >= 0) && (y0 <= Hl - 1);
        bool vy1 = (y0 + 1 >= 0) && (y0 + 1 <= Hl - 1);
        if (!((vx0 || vx1) && (vy0 || vy1))) continue;

        int x0c = min(max(x0, 0), Wl - 1);
        int x1c = min(max(x0 + 1, 0), Wl - 1);
        int y0c = min(max(y0, 0), Hl - 1);
        int y1c = min(max(y0 + 1, 0), Hl - 1);

        int base = loff + c * HWl;
        int4 off;
        off.x = (base + y0c * Wl + x0c) * EMBED * 2;
        off.y = (base + y0c * Wl + x1c) * EMBED * 2;
        off.z = (base + y1c * Wl + x0c) * EMBED * 2;
        off.w = (base + y1c * Wl + x1c) * EMBED * 2;

        float g00 = (vx0 && vy0) ? wx0 * wy0 : 0.f;
        float g01 = (vx1 && vy0) ? wx1 * wy0 : 0.f;
        float g10 = (vx0 && vy1) ? wx0 * wy1 : 0.f;
        float g11 = (vx1 && vy1) ? wx1 * wy1 : 0.f;

        int idx = atomicAdd(&s_nv, 1);
        s_off[idx] = off;
        s_tap[idx] = t * NG;
        __nv_bfloat162 lo = __floats2bfloat162_rn(g00, g01);
        __nv_bfloat162 hi = __floats2bfloat162_rn(g10, g11);
        s_g4[idx] = make_uint2(*(unsigned*)&lo, *(unsigned*)&hi);
    }
    __syncthreads();
    const int nv = s_nv;

    const int lane = tid & 31;
    const int tg   = tid >> 5;
    const int ch   = lane * 8;
    const int g    = lane >> 2;
    const char* fb = (const char*)g_fmT + ch * 2;

    float acc[8] = {};
    #pragma unroll 2
    for (int i = tg; i < nv; i += 8) {
        int4 off = s_off[i];
        uint2 gp = s_g4[i];
        float wsm = s_w[s_tap[i] + g];
        __nv_bfloat162 glo = B2(gp.x), ghi = B2(gp.y);
        __nv_bfloat162 w00 = __low2bfloat162(glo), w01 = __high2bfloat162(glo);
        __nv_bfloat162 w10 = __low2bfloat162(ghi), w11 = __high2bfloat162(ghi);

        uint4 q00 = __ldg((const uint4*)(fb + off.x));
        uint4 q01 = __ldg((const uint4*)(fb + off.y));
        uint4 q10 = __ldg((const uint4*)(fb + off.z));
        uint4 q11 = __ldg((const uint4*)(fb + off.w));

        __nv_bfloat162 b0 = __hmul2(B2(q00.x), w00);
        __nv_bfloat162 b1 = __hmul2(B2(q00.y), w00);
        __nv_bfloat162 b2 = __hmul2(B2(q00.z), w00);
        __nv_bfloat162 b3 = __hmul2(B2(q00.w), w00);
        b0 = __hfma2(B2(q01.x), w01, b0);
        b1 = __hfma2(B2(q01.y), w01, b1);
        b2 = __hfma2(B2(q01.z), w01, b2);
        b3 = __hfma2(B2(q01.w), w01, b3);
        b0 = __hfma2(B2(q10.x), w10, b0);
        b1 = __hfma2(B2(q10.y), w10, b1);
        b2 = __hfma2(B2(q10.z), w10, b2);
        b3 = __hfma2(B2(q10.w), w10, b3);
        b0 = __hfma2(B2(q11.x), w11, b0);
        b1 = __hfma2(B2(q11.y), w11, b1);
        b2 = __hfma2(B2(q11.z), w11, b2);
        b3 = __hfma2(B2(q11.w), w11, b3);

        float2 f0 = __bfloat1622float2(b0);
        float2 f1 = __bfloat1622float2(b1);
        float2 f2 = __bfloat1622float2(b2);
        float2 f3 = __bfloat1622float2(b3);
        acc[0] = fmaf(wsm, f0.x, acc[0]); acc[1] = fmaf(wsm, f0.y, acc[1]);
        acc[2] = fmaf(wsm, f1.x, acc[2]); acc[3] = fmaf(wsm, f1.y, acc[3]);
        acc[4] = fmaf(wsm, f2.x, acc[4]); acc[5] = fmaf(wsm, f2.y, acc[5]);
        acc[6] = fmaf(wsm, f3.x, acc[6]); acc[7] = fmaf(wsm, f3.y, acc[7]);
    }
    __syncthreads();                 // s_w now dead; safe to alias as s_part
    #pragma unroll
    for (int i = 0; i < 8; i++) s_part[tg][ch + i] = acc[i];
    __syncthreads();
    {
        float f = 0.f;
        #pragma unroll
        for (int k = 0; k < 8; k++) f += s_part[k][tid];
        s_f[tid] = f;
    }
    __syncthreads();

    // epilogue GEMV: out[a] = s_f @ Wout(bf16) + bias + inst
    const int j0 = lane * 8;
    const int kg = tg;
    float oa[8] = {};
    #pragma unroll 4
    for (int k = kg * 32; k < kg * 32 + 32; k++) {
        uint4 w = __ldg((const uint4*)(g_WoutB + k * EMBED + j0));
        float f = s_f[k];
        float2 w0 = __bfloat1622float2(B2(w.x));
        float2 w1 = __bfloat1622float2(B2(w.y));
        float2 w2 = __bfloat1622float2(B2(w.z));
        float2 w3 = __bfloat1622float2(B2(w.w));
        oa[0] += f * w0.x; oa[1] += f * w0.y;
        oa[2] += f * w1.x; oa[3] += f * w1.y;
        oa[4] += f * w2.x; oa[5] += f * w2.y;
        oa[6] += f * w3.x; oa[7] += f * w3.y;
    }
    __syncthreads();
    #pragma unroll
    for (int i = 0; i < 8; i++) s_part[kg][j0 + i] = oa[i];
    __syncthreads();
    {
        float v = 0.f;
        #pragma unroll
        for (int k = 0; k < 8; k++) v += s_part[k][tid];
        out[a * EMBED + tid] = v + bout[tid] + inst[a * EMBED + tid];
    }
}

// ---------------- launch: fork cvt+gemm parallel to transpose --------------
extern "C" void kernel_launch(void* const* d_in, const int* in_sizes, int n_in,
                              void* d_out, int out_size) {
    const float* inst = (const float*)d_in[0];
    const float* anch = (const float*)d_in[1];
    const float* kp   = (const float*)d_in[2];
    const float* fm0  = (const float*)d_in[3];
    const float* fm1  = (const float*)d_in[4];
    const float* fm2  = (const float*)d_in[5];
    const float* fm3  = (const float*)d_in[6];
    const float* proj = (const float*)d_in[7];
    const float* wh   = (const float*)d_in[8];
    const float* Ww   = (const float*)d_in[9];
    const float* bw   = (const float*)d_in[10];
    const float* Wo   = (const float*)d_in[11];
    const float* bo   = (const float*)d_in[12];
    float* out = (float*)d_out;

    static cudaStream_t s1 = nullptr;
    static cudaEvent_t eFork = nullptr, eJoin = nullptr;
    if (!s1) {
        cudaStreamCreateWithFlags(&s1, cudaStreamNonBlocking);
        cudaEventCreateWithFlags(&eFork, cudaEventDisableTiming);
        cudaEventCreateWithFlags(&eJoin, cudaEventDisableTiming);
    }

    cudaEventRecord(eFork, 0);
    cudaStreamWaitEvent(s1, eFork, 0);
    k_fcvt<<<(NA * EMBED / 4 + 255) / 256, 256, 0, s1>>>(inst, anch);
    k_wwcvt<<<EMBED * NW / 1024, 256, 0, s1>>>(Ww);
    k_gemm_bf<<<dim3(NW / GBN, (NA + GBM - 1) / GBM), 256, 0, s1>>>(bw);
    k_wcvt<<<EMBED * EMBED / 1024, 256, 0, s1>>>(Wo);
    cudaEventRecord(eJoin, s1);

    k_transpose<<<dim3(PBTOT, 4, NCAM), dim3(32, 8)>>>(fm0, fm1, fm2, fm3);

    cudaStreamWaitEvent(0, eJoin, 0);
    k_sample<<<NA, 256>>>(kp, proj, wh, inst, bo, out);
}